// round 10
// baseline (speedup 1.0000x reference)
#include <cuda_runtime.h>

// out_b = Wp (s_b ∘ (Wq X_b)) + X_b,  s_b[c] = sum_n (Wk X_b)[c,n]*(Wv X_b)[c,n]
// B=2, C=64, N=1024. 128 blocks x 512 threads, one wave, ONE grid barrier.
// Thread tile: 1 channel x 2 columns (cols nt, nt+8). Packed fma.rn.f32x2.

#define NBLK 128
#define NTHR 512
#define WS 68
#define XS 68

#define OFF_WK 0
#define OFF_WV (64 * WS)
#define OFF_WQ (2 * 64 * WS)
#define OFF_WP (3 * 64 * WS)
#define OFF_XT (4 * 64 * WS)
#define OFF_YS (OFF_XT + 16 * XS)
#define OFF_SS (OFF_YS + 16 * XS)
#define SMEM_FLOATS (OFF_SS + 64)

typedef unsigned long long u64;

__device__ float g_sPart[2][64][64];

__device__ unsigned g_cnt;
__device__ volatile unsigned g_flag;

__device__ __forceinline__ void gridbar() {
    __syncthreads();
    if (threadIdx.x == 0) {
        unsigned f0 = g_flag;
        __threadfence();
        unsigned old = atomicAdd(&g_cnt, 1u);
        if (old == NBLK - 1) {
            g_cnt = 0;
            __threadfence();
            atomicAdd((unsigned*)&g_flag, 1u);
        } else {
            while (g_flag == f0) { }
        }
        __threadfence();
    }
    __syncthreads();
}

__device__ __forceinline__ void fma2(u64& d, u64 a, u64 b) {
    asm("fma.rn.f32x2 %0, %1, %2, %0;" : "+l"(d) : "l"(a), "l"(b));
}
__device__ __forceinline__ u64 mul2(u64 a, u64 b) {
    u64 d;
    asm("mul.rn.f32x2 %0, %1, %2;" : "=l"(d) : "l"(a), "l"(b));
    return d;
}
__device__ __forceinline__ float hsum2(u64 v) {
    float lo, hi;
    asm("mov.b64 {%0, %1}, %2;" : "=f"(lo), "=f"(hi) : "l"(v));
    return lo + hi;
}

extern __shared__ float sm[];

__global__ void __launch_bounds__(NTHR) attn_fused(
    const float* __restrict__ x,
    const float* __restrict__ wq, const float* __restrict__ wk,
    const float* __restrict__ wv, const float* __restrict__ wp,
    float* __restrict__ out)
{
    const int tid = threadIdx.x;
    const int blk = blockIdx.x;
    const int b   = blk >> 6;
    const int ch  = blk & 63;
    const int n0  = ch * 16;

    const int nt = tid & 7;           // column pair: cols nt, nt+8
    const int c  = tid >> 3;          // channel (0..63)

    float* Xs = sm + OFF_XT;
    float* Ys = sm + OFF_YS;
    float* Ss = sm + OFF_SS;

    // ---- Stage all 4 weight matrices (padded rows) + X chunk ---------------
    {
        const float* srcs[4] = {wk, wv, wq, wp};
        #pragma unroll
        for (int i = 0; i < 8; i++) {
            const int e  = tid + NTHR * i;        // float4 index 0..4095
            const int m  = i >> 1;                // 512*2 = 1024 per matrix
            const int e2 = e & 1023;
            const int r  = e2 >> 4, c4 = e2 & 15;
            float4 v = ((const float4*)srcs[m])[e2];
            *(float4*)&sm[m * 64 * WS + r * WS + c4 * 4] = v;
        }
        const float* xb = x + b * 65536 + n0;
        #pragma unroll
        for (int i = 0; i < 2; i++) {
            const int e = tid + NTHR * i;         // e = c*16 + n
            Xs[(e & 15) * XS + (e >> 4)] = xb[(e >> 4) * 1024 + (e & 15)];
        }
    }
    __syncthreads();

    // ---- Fused K/V/Q projections (packed f32x2 along j) --------------------
    {
        const ulonglong2* WkR = (const ulonglong2*)&sm[OFF_WK + c * WS];
        const ulonglong2* WvR = (const ulonglong2*)&sm[OFF_WV + c * WS];
        const ulonglong2* WqR = (const ulonglong2*)&sm[OFF_WQ + c * WS];
        const ulonglong2* X0  = (const ulonglong2*)&Xs[nt * XS];
        const ulonglong2* X1  = (const ulonglong2*)&Xs[(nt + 8) * XS];

        u64 K0 = 0, K1 = 0, V0 = 0, V1 = 0, Q0 = 0, Q1 = 0;

        #pragma unroll
        for (int jg = 0; jg < 16; jg++) {
            ulonglong2 xa = X0[jg], xb2 = X1[jg];
            ulonglong2 w;
            w = WkR[jg];
            fma2(K0, w.x, xa.x);  fma2(K0, w.y, xa.y);
            fma2(K1, w.x, xb2.x); fma2(K1, w.y, xb2.y);
            w = WvR[jg];
            fma2(V0, w.x, xa.x);  fma2(V0, w.y, xa.y);
            fma2(V1, w.x, xb2.x); fma2(V1, w.y, xb2.y);
            w = WqR[jg];
            fma2(Q0, w.x, xa.x);  fma2(Q0, w.y, xa.y);
            fma2(Q1, w.x, xb2.x); fma2(Q1, w.y, xb2.y);
        }

        // Unscaled Y into smem ([n][c]).
        Ys[nt * XS + c]       = hsum2(Q0);
        Ys[(nt + 8) * XS + c] = hsum2(Q1);

        // s partial: K·V over this thread's 2 cols, reduce over 8-lane group.
        float s = hsum2(K0) * hsum2(V0) + hsum2(K1) * hsum2(V1);
        s += __shfl_down_sync(0xffffffffu, s, 4, 8);
        s += __shfl_down_sync(0xffffffffu, s, 2, 8);
        s += __shfl_down_sync(0xffffffffu, s, 1, 8);
        if (nt == 0) g_sPart[b][c][ch] = s;
    }

    gridbar();

    // ---- Reduce s (8 threads/channel, fixed order -> deterministic) --------
    {
        const int c2 = tid >> 3, q = tid & 7;
        const float4* sp = (const float4*)&g_sPart[b][c2][q * 8];
        float4 a = __ldcg(&sp[0]);
        float4 d = __ldcg(&sp[1]);
        float v = a.x + a.y + a.z + a.w + d.x + d.y + d.z + d.w;
        v += __shfl_down_sync(0xffffffffu, v, 4, 8);
        v += __shfl_down_sync(0xffffffffu, v, 2, 8);
        v += __shfl_down_sync(0xffffffffu, v, 1, 8);
        if (q == 0) Ss[c2] = v;
    }
    __syncthreads();

    // ---- out = Wp · (s ∘ Ys) + X  (packed f32x2, s folded in) --------------
    {
        const ulonglong2* WpR = (const ulonglong2*)&sm[OFF_WP + c * WS];
        const ulonglong2* Y0  = (const ulonglong2*)&Ys[nt * XS];
        const ulonglong2* Y1  = (const ulonglong2*)&Ys[(nt + 8) * XS];
        const ulonglong2* S2  = (const ulonglong2*)Ss;

        u64 O0 = 0, O1 = 0;
        #pragma unroll
        for (int jg = 0; jg < 16; jg++) {
            ulonglong2 ss = S2[jg];
            ulonglong2 y0 = Y0[jg], y1 = Y1[jg];
            ulonglong2 w  = WpR[jg];
            fma2(O0, w.x, mul2(y0.x, ss.x)); fma2(O0, w.y, mul2(y0.y, ss.y));
            fma2(O1, w.x, mul2(y1.x, ss.x)); fma2(O1, w.y, mul2(y1.y, ss.y));
        }
        float* ob = out + b * 65536 + n0;
        ob[c * 1024 + nt]     = hsum2(O0) + Xs[nt * XS + c];
        ob[c * 1024 + nt + 8] = hsum2(O1) + Xs[(nt + 8) * XS + c];
    }
}

extern "C" void kernel_launch(void* const* d_in, const int* in_sizes, int n_in,
                              void* d_out, int out_size) {
    const float* x  = (const float*)d_in[0];
    const float* wq = (const float*)d_in[1];
    const float* wk = (const float*)d_in[2];
    const float* wv = (const float*)d_in[3];
    const float* wp = (const float*)d_in[4];

    static int smem_set = 0;
    if (!smem_set) {
        cudaFuncSetAttribute(attn_fused, cudaFuncAttributeMaxDynamicSharedMemorySize,
                             SMEM_FLOATS * (int)sizeof(float));
        smem_set = 1;
    }
    attn_fused<<<NBLK, NTHR, SMEM_FLOATS * sizeof(float)>>>(
        x, wq, wk, wv, wp, (float*)d_out);
}